// round 4
// baseline (speedup 1.0000x reference)
#include <cuda_runtime.h>
#include <cstdint>

typedef unsigned long long u64;
typedef unsigned int u32;

#define NUM_CITIES 50000
#define EMB 50
#define HID 64
#define G4 256          // 4 * HID
#define BATCH 1024
#define SEQ 512
#define K3_CTAS 196     // ceil(50000/256)

// Scratch (no allocation allowed -> device globals)
__device__ float g_emb_proj[NUM_CITIES * G4];     // emb @ W_ih^T + bias, 51.2MB
__device__ float g_hfin[BATCH * HID];             // final hidden state
__device__ float g_partial[K3_CTAS * BATCH];      // per-CTA row partial sums
__device__ float g_rowinv[BATCH];                 // 1/rowsum

// ---------------------------------------------------------------------------
// helpers
// ---------------------------------------------------------------------------
__device__ __forceinline__ float fast_ex2(float x) {
    float r; asm("ex2.approx.f32 %0, %1;" : "=f"(r) : "f"(x)); return r;
}
__device__ __forceinline__ float fast_rcp(float x) {
    float r; asm("rcp.approx.f32 %0, %1;" : "=f"(r) : "f"(x)); return r;
}
__device__ __forceinline__ float sigmoid_(float x) {
    return fast_rcp(1.0f + fast_ex2(-1.4426950408889634f * x));
}
__device__ __forceinline__ float tanh_(float x) {
    return fmaf(2.0f, sigmoid_(2.0f * x), -1.0f);
}
__device__ __forceinline__ void unpack2(u64 v, float& lo, float& hi) {
    asm("mov.b64 {%0,%1}, %2;" : "=f"(lo), "=f"(hi) : "l"(v));
}
__device__ __forceinline__ u64 pack2(float lo, float hi) {
    u64 v; asm("mov.b64 %0, {%1,%2};" : "=l"(v) : "f"(lo), "f"(hi)); return v;
}
// non-volatile packed FMA: compiler/ptxas free to schedule
__device__ __forceinline__ void fma2(u64& acc, u64 a, u64 b) {
    asm("fma.rn.f32x2 %0, %1, %2, %0;" : "+l"(acc) : "l"(a), "l"(b));
}

// ---------------------------------------------------------------------------
// K1: emb_proj[r][j] = sum_k emb[r][k]*W_ih[j][k] + (b_ih[j]+b_hh[j])
// 625 CTAs x 256 threads, 80 rows per CTA. thread = gate column j.
// ---------------------------------------------------------------------------
__global__ void __launch_bounds__(256) k1_embproj(
    const float* __restrict__ emb, const float* __restrict__ W_ih,
    const float* __restrict__ b_ih, const float* __restrict__ b_hh)
{
    __shared__ __align__(16) float es[80][52];   // padded; [50..52)=0
    const int j  = threadIdx.x;
    const int r0 = blockIdx.x * 80;

    // W_ih row j as 25 float2 (k pairs) + zero tail pair
    u64 wk[26];
    {
        const float2* wr = reinterpret_cast<const float2*>(W_ih + j * 50);
#pragma unroll
        for (int m = 0; m < 25; m++) {
            float2 t = __ldg(&wr[m]);
            wk[m] = pack2(t.x, t.y);
        }
        wk[25] = 0ull;
    }
    const u64 biasp = pack2(b_ih[j] + b_hh[j], 0.0f);

    for (int idx = j; idx < 80 * 50; idx += 256)
        es[idx / 50][idx % 50] = emb[(r0 + idx / 50) * 50 + (idx % 50)];
    if (j < 160) es[j >> 1][50 + (j & 1)] = 0.0f;
    __syncthreads();

#pragma unroll 4
    for (int r = 0; r < 80; r++) {
        u64 acc = biasp;
#pragma unroll
        for (int m = 0; m < 13; m++) {
            ulonglong2 e2 = *reinterpret_cast<const ulonglong2*>(&es[r][m * 4]);
            fma2(acc, e2.x, wk[2 * m]);
            fma2(acc, e2.y, wk[2 * m + 1]);
        }
        float lo, hi; unpack2(acc, lo, hi);
        g_emb_proj[(r0 + r) * G4 + j] = lo + hi;
    }
}

// ---------------------------------------------------------------------------
// K2: LSTM recurrence. 128 CTAs x 256 threads, 8 batch rows per CTA.
// Thread t: columns j0 = t&127, j1 = (t&127)+128; batches 4*(t>>7)..+3.
// Gate order: [0,64)=i [64,128)=f [128,192)=g(tanh) [192,256)=o
// ---------------------------------------------------------------------------
__global__ void __launch_bounds__(256) k2_lstm(
    const int* __restrict__ x, const float* __restrict__ W_hh)
{
    __shared__ __align__(16) float hS[8][64];
    __shared__ float gS[8][256];
    __shared__ int   xs[2][8];

    const int tid = threadIdx.x;
    const int jc  = tid & 127;
    const int j0  = jc;            // gate 0 or 1  -> sigmoid
    const int j1  = jc + 128;      // gate 2 or 3  -> tanh if jc<64 else sigmoid
    const bool j1_tanh = (jc < 64);
    const int bh  = (tid >> 7) * 4;    // batch base: 0 or 4
    const int b0  = blockIdx.x * 8;

    // W_hh rows j0, j1 packed as f32x2 over k-pairs
    u64 w0[32], w1[32];
    {
        const ulonglong2* r0p = reinterpret_cast<const ulonglong2*>(W_hh + j0 * HID);
        const ulonglong2* r1p = reinterpret_cast<const ulonglong2*>(W_hh + j1 * HID);
#pragma unroll
        for (int q = 0; q < 16; q++) {
            ulonglong2 a = __ldg(&r0p[q]); w0[2*q] = a.x; w0[2*q+1] = a.y;
            ulonglong2 b = __ldg(&r1p[q]); w1[2*q] = b.x; w1[2*q+1] = b.y;
        }
    }

    // zero h
    hS[tid >> 5][tid & 31]        = 0.0f;
    hS[tid >> 5][(tid & 31) + 32] = 0.0f;
    if (tid < 8) xs[0][tid] = x[(b0 + tid) * SEQ];

    // update-phase ownership: (b,k) pairs tid and tid+256
    const int ub0 = tid >> 6,      uk0 = tid & 63;
    const int ub1 = (tid >> 6) + 4, uk1 = tid & 63;
    float c0 = 0.0f, c1 = 0.0f, hl0 = 0.0f, hl1 = 0.0f;

    __syncthreads();

    for (int t = 0; t < SEQ; t++) {
        const int cur = t & 1;

        // gather gx early (L2-resident table)
        float gx0[4], gx1[4];
#pragma unroll
        for (int b = 0; b < 4; b++) {
            const float* row = g_emb_proj + (size_t)xs[cur][bh + b] * G4;
            gx0[b] = __ldg(row + j0);
            gx1[b] = __ldg(row + j1);
        }

        // matvec: per batch, acc lanes = (even-k, odd-k) partials
        u64 a0[4], a1[4];
#pragma unroll
        for (int b = 0; b < 4; b++) { a0[b] = 0ull; a1[b] = 0ull; }
#pragma unroll
        for (int q = 0; q < 16; q++) {
#pragma unroll
            for (int b = 0; b < 4; b++) {
                ulonglong2 hv = *reinterpret_cast<const ulonglong2*>(&hS[bh + b][q * 4]);
                fma2(a0[b], hv.x, w0[2*q]);
                fma2(a1[b], hv.x, w1[2*q]);
                fma2(a0[b], hv.y, w0[2*q+1]);
                fma2(a1[b], hv.y, w1[2*q+1]);
            }
        }

        // prefetch next token indices
        if (tid < 8 && t + 1 < SEQ) xs[cur ^ 1][tid] = x[(b0 + tid) * SEQ + t + 1];

        // activations + gate store
#pragma unroll
        for (int b = 0; b < 4; b++) {
            float lo, hi;
            unpack2(a0[b], lo, hi);
            gS[bh + b][j0] = sigmoid_(lo + hi + gx0[b]);
            unpack2(a1[b], lo, hi);
            float v1 = lo + hi + gx1[b];
            gS[bh + b][j1] = j1_tanh ? tanh_(v1) : sigmoid_(v1);
        }
        __syncthreads();

        // update: each thread owns 2 (batch,column) pairs
        {
            float i_ = gS[ub0][uk0], f_ = gS[ub0][64 + uk0];
            float g_ = gS[ub0][128 + uk0], o_ = gS[ub0][192 + uk0];
            c0  = fmaf(f_, c0, i_ * g_);
            hl0 = o_ * tanh_(c0);
            hS[ub0][uk0] = hl0;
        }
        {
            float i_ = gS[ub1][uk1], f_ = gS[ub1][64 + uk1];
            float g_ = gS[ub1][128 + uk1], o_ = gS[ub1][192 + uk1];
            c1  = fmaf(f_, c1, i_ * g_);
            hl1 = o_ * tanh_(c1);
            hS[ub1][uk1] = hl1;
        }
        __syncthreads();
    }

    g_hfin[(b0 + ub0) * HID + uk0] = hl0;
    g_hfin[(b0 + ub1) * HID + uk1] = hl1;
}

// ---------------------------------------------------------------------------
// K3: out[b][c] = exp(h[b].W_fc[c] + b_fc[c]); per-CTA row partial sums
// ---------------------------------------------------------------------------
__global__ void __launch_bounds__(256) k3_fc(
    const float* __restrict__ W_fc, const float* __restrict__ b_fc,
    float* __restrict__ out)
{
    __shared__ __align__(16) float hS[16][64];
    __shared__ float ws[8][16];

    const int tid  = threadIdx.x;
    const int wid  = tid >> 5;
    const int lane = tid & 31;
    const int c    = blockIdx.x * 256 + tid;
    const bool valid = (c < NUM_CITIES);

    u64 wk[32];
    float bias = 0.0f;
    if (valid) {
        const ulonglong2* wr = reinterpret_cast<const ulonglong2*>(W_fc + c * HID);
#pragma unroll
        for (int q = 0; q < 16; q++) { ulonglong2 t = __ldg(&wr[q]); wk[2*q] = t.x; wk[2*q+1] = t.y; }
        bias = b_fc[c];
    } else {
#pragma unroll
        for (int q = 0; q < 32; q++) wk[q] = 0ull;
    }

    for (int bc = 0; bc < BATCH; bc += 16) {
        __syncthreads();
        reinterpret_cast<float4*>(hS)[tid] =
            reinterpret_cast<const float4*>(g_hfin + bc * HID)[tid];
        __syncthreads();

        u64 acc[16];
#pragma unroll
        for (int b = 0; b < 16; b++) acc[b] = 0ull;

#pragma unroll
        for (int q = 0; q < 16; q++) {
#pragma unroll
            for (int b = 0; b < 16; b++) {
                ulonglong2 hv = *reinterpret_cast<const ulonglong2*>(&hS[b][q * 4]);
                fma2(acc[b], hv.x, wk[2*q]);
                fma2(acc[b], hv.y, wk[2*q+1]);
            }
        }

#pragma unroll
        for (int b = 0; b < 16; b++) {
            float lo, hi;
            unpack2(acc[b], lo, hi);
            float l = lo + hi + bias;
            float e = fast_ex2(l * 1.4426950408889634f);
            float ev = valid ? e : 0.0f;
            if (valid) __stcs(&out[(size_t)(bc + b) * NUM_CITIES + c], e);
            ev += __shfl_xor_sync(0xffffffffu, ev, 16);
            ev += __shfl_xor_sync(0xffffffffu, ev, 8);
            ev += __shfl_xor_sync(0xffffffffu, ev, 4);
            ev += __shfl_xor_sync(0xffffffffu, ev, 2);
            ev += __shfl_xor_sync(0xffffffffu, ev, 1);
            if (lane == 0) ws[wid][b] = ev;
        }
        __syncthreads();

        if (tid < 16) {
            float s = 0.0f;
#pragma unroll
            for (int w = 0; w < 8; w++) s += ws[w][tid];
            g_partial[blockIdx.x * BATCH + bc + tid] = s;
        }
    }
}

// ---------------------------------------------------------------------------
// K3c: exact row-sum inverses. 256 CTAs x 128 threads; one warp per batch row.
// ---------------------------------------------------------------------------
__global__ void __launch_bounds__(128) k3c_inv()
{
    const int warp = (blockIdx.x * 128 + threadIdx.x) >> 5;   // 0..1023
    const int lane = threadIdx.x & 31;
    float s = 0.0f;
    for (int cta = lane; cta < K3_CTAS; cta += 32)
        s += g_partial[cta * BATCH + warp];
    s += __shfl_xor_sync(0xffffffffu, s, 16);
    s += __shfl_xor_sync(0xffffffffu, s, 8);
    s += __shfl_xor_sync(0xffffffffu, s, 4);
    s += __shfl_xor_sync(0xffffffffu, s, 2);
    s += __shfl_xor_sync(0xffffffffu, s, 1);
    if (lane == 0) g_rowinv[warp] = 1.0f / s;
}

// ---------------------------------------------------------------------------
// K4: pure streaming scale. One float4 per thread.
// ---------------------------------------------------------------------------
__global__ void __launch_bounds__(256) k4_scale(float4* __restrict__ out4)
{
    const int i = blockIdx.x * 256 + threadIdx.x;    // < 12,800,000
    const int b = i / (NUM_CITIES / 4);
    const float inv = g_rowinv[b];
    float4 v = __ldcs(&out4[i]);
    v.x *= inv; v.y *= inv; v.z *= inv; v.w *= inv;
    __stcs(&out4[i], v);
}

// ---------------------------------------------------------------------------
extern "C" void kernel_launch(void* const* d_in, const int* in_sizes, int n_in,
                              void* d_out, int out_size)
{
    (void)in_sizes; (void)n_in; (void)out_size;
    const int*   x    = (const int*)  d_in[0];
    const float* emb  = (const float*)d_in[1];
    const float* W_ih = (const float*)d_in[2];
    const float* W_hh = (const float*)d_in[3];
    const float* b_ih = (const float*)d_in[4];
    const float* b_hh = (const float*)d_in[5];
    const float* W_fc = (const float*)d_in[6];
    const float* b_fc = (const float*)d_in[7];
    float* out = (float*)d_out;

    k1_embproj<<<NUM_CITIES / 80, 256>>>(emb, W_ih, b_ih, b_hh);
    k2_lstm<<<BATCH / 8, 256>>>(x, W_hh);
    k3_fc<<<K3_CTAS, 256>>>(W_fc, b_fc, out);
    k3c_inv<<<256, 128>>>();
    k4_scale<<<(BATCH * NUM_CITIES / 4) / 256, 256>>>((float4*)out);
}

// round 5
// speedup vs baseline: 1.2409x; 1.2409x over previous
#include <cuda_runtime.h>
#include <cstdint>

typedef unsigned long long u64;
typedef unsigned int u32;

#define NUM_CITIES 50000
#define EMB 50
#define HID 64
#define G4 256          // 4 * HID
#define BATCH 1024
#define SEQ 512
#define K3_CTAS 196     // ceil(50000/256)

// Scratch (no allocation allowed -> device globals)
__device__ float g_emb_proj[NUM_CITIES * G4];     // emb @ W_ih^T + bias, 51.2MB
__device__ float g_hfin[BATCH * HID];             // final hidden state
__device__ float g_partial[K3_CTAS * BATCH];      // per-CTA row partial sums
__device__ float g_rowinv[BATCH];                 // 1/rowsum

// ---------------------------------------------------------------------------
// helpers
// ---------------------------------------------------------------------------
__device__ __forceinline__ float fast_ex2(float x) {
    float r; asm("ex2.approx.f32 %0, %1;" : "=f"(r) : "f"(x)); return r;
}
__device__ __forceinline__ float fast_rcp(float x) {
    float r; asm("rcp.approx.f32 %0, %1;" : "=f"(r) : "f"(x)); return r;
}
__device__ __forceinline__ float sigmoid_(float x) {
    return fast_rcp(1.0f + fast_ex2(-1.4426950408889634f * x));
}
__device__ __forceinline__ float tanh_(float x) {
    return fmaf(2.0f, sigmoid_(2.0f * x), -1.0f);
}
__device__ __forceinline__ void unpack2(u64 v, float& lo, float& hi) {
    asm("mov.b64 {%0,%1}, %2;" : "=f"(lo), "=f"(hi) : "l"(v));
}
__device__ __forceinline__ u64 pack2(float lo, float hi) {
    u64 v; asm("mov.b64 %0, {%1,%2};" : "=l"(v) : "f"(lo), "f"(hi)); return v;
}
// non-volatile packed FMA: compiler/ptxas free to schedule
__device__ __forceinline__ void fma2(u64& acc, u64 a, u64 b) {
    asm("fma.rn.f32x2 %0, %1, %2, %0;" : "+l"(acc) : "l"(a), "l"(b));
}

// no-op launch-slot shifter (so ncu's fixed sample index lands on k2)
__global__ void k_nop() {}

// ---------------------------------------------------------------------------
// K1: emb_proj[r][j] = sum_k emb[r][k]*W_ih[j][k] + (b_ih[j]+b_hh[j])
// 625 CTAs x 256 threads, 80 rows per CTA. thread = gate column j.
// ---------------------------------------------------------------------------
__global__ void __launch_bounds__(256) k1_embproj(
    const float* __restrict__ emb, const float* __restrict__ W_ih,
    const float* __restrict__ b_ih, const float* __restrict__ b_hh)
{
    __shared__ __align__(16) float es[80][52];   // padded; [50..52)=0
    const int j  = threadIdx.x;
    const int r0 = blockIdx.x * 80;

    u64 wk[26];
    {
        const float2* wr = reinterpret_cast<const float2*>(W_ih + j * 50);
#pragma unroll
        for (int m = 0; m < 25; m++) {
            float2 t = __ldg(&wr[m]);
            wk[m] = pack2(t.x, t.y);
        }
        wk[25] = 0ull;
    }
    const u64 biasp = pack2(b_ih[j] + b_hh[j], 0.0f);

    for (int idx = j; idx < 80 * 50; idx += 256)
        es[idx / 50][idx % 50] = emb[(r0 + idx / 50) * 50 + (idx % 50)];
    if (j < 160) es[j >> 1][50 + (j & 1)] = 0.0f;
    __syncthreads();

#pragma unroll 4
    for (int r = 0; r < 80; r++) {
        u64 acc = biasp;
#pragma unroll
        for (int m = 0; m < 13; m++) {
            ulonglong2 e2 = *reinterpret_cast<const ulonglong2*>(&es[r][m * 4]);
            fma2(acc, e2.x, wk[2 * m]);
            fma2(acc, e2.y, wk[2 * m + 1]);
        }
        float lo, hi; unpack2(acc, lo, hi);
        g_emb_proj[(r0 + r) * G4 + j] = lo + hi;
    }
}

// ---------------------------------------------------------------------------
// K2: LSTM recurrence. 256 CTAs x 256 threads, 4 batch rows per CTA,
// 2 CTAs co-resident per SM (launch_bounds) so one CTA's matvec overlaps the
// other's barrier/update phase.
// Thread = gate column j (W_hh row j in 32 u64 regs), all 4 batches.
// Gate order: [0,64)=i [64,128)=f [128,192)=g(tanh) [192,256)=o
// ---------------------------------------------------------------------------
__global__ void __launch_bounds__(256, 2) k2_lstm(
    const int* __restrict__ x, const float* __restrict__ W_hh)
{
    __shared__ __align__(16) float hS[4][64];
    __shared__ float gS[4][256];
    __shared__ int   xs[2][4];

    const int tid = threadIdx.x;
    const int j   = tid;
    const int b0  = blockIdx.x * 4;
    const int gate = j >> 6;

    // W_hh row j packed as f32x2 over k-pairs
    u64 wk[32];
    {
        const ulonglong2* wr = reinterpret_cast<const ulonglong2*>(W_hh + j * HID);
#pragma unroll
        for (int q = 0; q < 16; q++) {
            ulonglong2 t = __ldg(&wr[q]); wk[2*q] = t.x; wk[2*q+1] = t.y;
        }
    }

    hS[tid >> 6][tid & 63] = 0.0f;
    if (tid < 4) xs[0][tid] = x[(b0 + tid) * SEQ];

    const int ub = tid >> 6;   // update batch (0..3)
    const int uk = tid & 63;   // update column
    float c  = 0.0f;
    float hl = 0.0f;

    __syncthreads();

    for (int t = 0; t < SEQ; t++) {
        const int cur = t & 1;

        // gather gx early (L2-resident table)
        float gx[4];
#pragma unroll
        for (int b = 0; b < 4; b++)
            gx[b] = __ldg(g_emb_proj + (size_t)xs[cur][b] * G4 + j);

        // matvec: per batch, acc lanes = (even-k, odd-k) partials
        u64 a0 = 0ull, a1 = 0ull, a2 = 0ull, a3 = 0ull;
#pragma unroll
        for (int q = 0; q < 16; q++) {
            ulonglong2 h0 = *reinterpret_cast<const ulonglong2*>(&hS[0][q * 4]);
            ulonglong2 h1 = *reinterpret_cast<const ulonglong2*>(&hS[1][q * 4]);
            ulonglong2 h2 = *reinterpret_cast<const ulonglong2*>(&hS[2][q * 4]);
            ulonglong2 h3 = *reinterpret_cast<const ulonglong2*>(&hS[3][q * 4]);
            fma2(a0, h0.x, wk[2*q]);  fma2(a0, h0.y, wk[2*q+1]);
            fma2(a1, h1.x, wk[2*q]);  fma2(a1, h1.y, wk[2*q+1]);
            fma2(a2, h2.x, wk[2*q]);  fma2(a2, h2.y, wk[2*q+1]);
            fma2(a3, h3.x, wk[2*q]);  fma2(a3, h3.y, wk[2*q+1]);
        }

        // prefetch next token indices
        if (tid < 4 && t + 1 < SEQ) xs[cur ^ 1][tid] = x[(b0 + tid) * SEQ + t + 1];

        // activations + gate store
        {
            float lo, hi, v;
            unpack2(a0, lo, hi); v = lo + hi + gx[0];
            gS[0][j] = (gate == 2) ? tanh_(v) : sigmoid_(v);
            unpack2(a1, lo, hi); v = lo + hi + gx[1];
            gS[1][j] = (gate == 2) ? tanh_(v) : sigmoid_(v);
            unpack2(a2, lo, hi); v = lo + hi + gx[2];
            gS[2][j] = (gate == 2) ? tanh_(v) : sigmoid_(v);
            unpack2(a3, lo, hi); v = lo + hi + gx[3];
            gS[3][j] = (gate == 2) ? tanh_(v) : sigmoid_(v);
        }
        __syncthreads();

        // update: one thread per (batch, column) -- exactly 256 pairs
        {
            float i_ = gS[ub][uk];
            float f_ = gS[ub][64 + uk];
            float g_ = gS[ub][128 + uk];
            float o_ = gS[ub][192 + uk];
            c  = fmaf(f_, c, i_ * g_);
            hl = o_ * tanh_(c);
            hS[ub][uk] = hl;
        }
        __syncthreads();
    }

    g_hfin[(b0 + ub) * HID + uk] = hl;
}

// ---------------------------------------------------------------------------
// K3: out[b][c] = exp(h[b].W_fc[c] + b_fc[c]); per-CTA row partial sums
// ---------------------------------------------------------------------------
__global__ void __launch_bounds__(256) k3_fc(
    const float* __restrict__ W_fc, const float* __restrict__ b_fc,
    float* __restrict__ out)
{
    __shared__ __align__(16) float hS[16][64];
    __shared__ float ws[8][16];

    const int tid  = threadIdx.x;
    const int wid  = tid >> 5;
    const int lane = tid & 31;
    const int c    = blockIdx.x * 256 + tid;
    const bool valid = (c < NUM_CITIES);

    u64 wk[32];
    float bias = 0.0f;
    if (valid) {
        const ulonglong2* wr = reinterpret_cast<const ulonglong2*>(W_fc + c * HID);
#pragma unroll
        for (int q = 0; q < 16; q++) { ulonglong2 t = __ldg(&wr[q]); wk[2*q] = t.x; wk[2*q+1] = t.y; }
        bias = b_fc[c];
    } else {
#pragma unroll
        for (int q = 0; q < 32; q++) wk[q] = 0ull;
    }

    for (int bc = 0; bc < BATCH; bc += 16) {
        __syncthreads();
        reinterpret_cast<float4*>(hS)[tid] =
            reinterpret_cast<const float4*>(g_hfin + bc * HID)[tid];
        __syncthreads();

        u64 acc[16];
#pragma unroll
        for (int b = 0; b < 16; b++) acc[b] = 0ull;

#pragma unroll
        for (int q = 0; q < 16; q++) {
#pragma unroll
            for (int b = 0; b < 16; b++) {
                ulonglong2 hv = *reinterpret_cast<const ulonglong2*>(&hS[b][q * 4]);
                fma2(acc[b], hv.x, wk[2*q]);
                fma2(acc[b], hv.y, wk[2*q+1]);
            }
        }

#pragma unroll
        for (int b = 0; b < 16; b++) {
            float lo, hi;
            unpack2(acc[b], lo, hi);
            float l = lo + hi + bias;
            float e = fast_ex2(l * 1.4426950408889634f);
            float ev = valid ? e : 0.0f;
            if (valid) __stcs(&out[(size_t)(bc + b) * NUM_CITIES + c], e);
            ev += __shfl_xor_sync(0xffffffffu, ev, 16);
            ev += __shfl_xor_sync(0xffffffffu, ev, 8);
            ev += __shfl_xor_sync(0xffffffffu, ev, 4);
            ev += __shfl_xor_sync(0xffffffffu, ev, 2);
            ev += __shfl_xor_sync(0xffffffffu, ev, 1);
            if (lane == 0) ws[wid][b] = ev;
        }
        __syncthreads();

        if (tid < 16) {
            float s = 0.0f;
#pragma unroll
            for (int w = 0; w < 8; w++) s += ws[w][tid];
            g_partial[blockIdx.x * BATCH + bc + tid] = s;
        }
    }
}

// ---------------------------------------------------------------------------
// K3c: exact row-sum inverses. 256 CTAs x 128 threads; one warp per batch row.
// ---------------------------------------------------------------------------
__global__ void __launch_bounds__(128) k3c_inv()
{
    const int warp = (blockIdx.x * 128 + threadIdx.x) >> 5;   // 0..1023
    const int lane = threadIdx.x & 31;
    float s = 0.0f;
    for (int cta = lane; cta < K3_CTAS; cta += 32)
        s += g_partial[cta * BATCH + warp];
    s += __shfl_xor_sync(0xffffffffu, s, 16);
    s += __shfl_xor_sync(0xffffffffu, s, 8);
    s += __shfl_xor_sync(0xffffffffu, s, 4);
    s += __shfl_xor_sync(0xffffffffu, s, 2);
    s += __shfl_xor_sync(0xffffffffu, s, 1);
    if (lane == 0) g_rowinv[warp] = 1.0f / s;
}

// ---------------------------------------------------------------------------
// K4: pure streaming scale. One float4 per thread.
// ---------------------------------------------------------------------------
__global__ void __launch_bounds__(256) k4_scale(float4* __restrict__ out4)
{
    const int i = blockIdx.x * 256 + threadIdx.x;    // < 12,800,000
    const int b = i / (NUM_CITIES / 4);
    const float inv = g_rowinv[b];
    float4 v = __ldcs(&out4[i]);
    v.x *= inv; v.y *= inv; v.z *= inv; v.w *= inv;
    __stcs(&out4[i], v);
}

// ---------------------------------------------------------------------------
extern "C" void kernel_launch(void* const* d_in, const int* in_sizes, int n_in,
                              void* d_out, int out_size)
{
    (void)in_sizes; (void)n_in; (void)out_size;
    const int*   x    = (const int*)  d_in[0];
    const float* emb  = (const float*)d_in[1];
    const float* W_ih = (const float*)d_in[2];
    const float* W_hh = (const float*)d_in[3];
    const float* b_ih = (const float*)d_in[4];
    const float* b_hh = (const float*)d_in[5];
    const float* W_fc = (const float*)d_in[6];
    const float* b_fc = (const float*)d_in[7];
    float* out = (float*)d_out;

    k1_embproj<<<NUM_CITIES / 80, 256>>>(emb, W_ih, b_ih, b_hh);
    k_nop<<<1, 32>>>();
    k_nop<<<1, 32>>>();
    k2_lstm<<<BATCH / 4, 256>>>(x, W_hh);
    k3_fc<<<K3_CTAS, 256>>>(W_fc, b_fc, out);
    k3c_inv<<<256, 128>>>();
    k4_scale<<<(BATCH * NUM_CITIES / 4) / 256, 256>>>((float4*)out);
}

// round 6
// speedup vs baseline: 1.4735x; 1.1875x over previous
#include <cuda_runtime.h>
#include <cuda_fp16.h>
#include <cstdint>

typedef unsigned long long u64;
typedef unsigned int u32;

#define NUM_CITIES 50000
#define EMB 50
#define HID 64
#define G4 256          // 4 * HID
#define BATCH 1024
#define SEQ 512
#define K3_CTAS 196     // ceil(50000/256)
#define HSTRIDE 72      // fp16 h row stride (halfs) -> conflict-free B-frag LDS

// Scratch (no allocation allowed -> device globals)
__device__ float g_emb_proj[NUM_CITIES * G4];     // emb @ W_ih^T + bias, 51.2MB
__device__ float g_hfin[BATCH * HID];             // final hidden state
__device__ float g_partial[K3_CTAS * BATCH];      // per-CTA row partial sums
__device__ float g_rowinv[BATCH];                 // 1/rowsum

// ---------------------------------------------------------------------------
// helpers
// ---------------------------------------------------------------------------
__device__ __forceinline__ float fast_ex2(float x) {
    float r; asm("ex2.approx.f32 %0, %1;" : "=f"(r) : "f"(x)); return r;
}
__device__ __forceinline__ float fast_rcp(float x) {
    float r; asm("rcp.approx.f32 %0, %1;" : "=f"(r) : "f"(x)); return r;
}
__device__ __forceinline__ float sigmoid_(float x) {
    return fast_rcp(1.0f + fast_ex2(-1.4426950408889634f * x));
}
__device__ __forceinline__ float tanh_(float x) {
    return fmaf(2.0f, sigmoid_(2.0f * x), -1.0f);
}
__device__ __forceinline__ void unpack2(u64 v, float& lo, float& hi) {
    asm("mov.b64 {%0,%1}, %2;" : "=f"(lo), "=f"(hi) : "l"(v));
}
__device__ __forceinline__ u64 pack2(float lo, float hi) {
    u64 v; asm("mov.b64 %0, {%1,%2};" : "=l"(v) : "f"(lo), "f"(hi)); return v;
}
__device__ __forceinline__ void fma2(u64& acc, u64 a, u64 b) {
    asm("fma.rn.f32x2 %0, %1, %2, %0;" : "+l"(acc) : "l"(a), "l"(b));
}
__device__ __forceinline__ void hmma16816(
    float& d0, float& d1, float& d2, float& d3,
    u32 a0, u32 a1, u32 a2, u32 a3, u32 b0, u32 b1)
{
    asm("mma.sync.aligned.m16n8k16.row.col.f32.f16.f16.f32 "
        "{%0,%1,%2,%3}, {%4,%5,%6,%7}, {%8,%9}, {%0,%1,%2,%3};"
        : "+f"(d0), "+f"(d1), "+f"(d2), "+f"(d3)
        : "r"(a0), "r"(a1), "r"(a2), "r"(a3), "r"(b0), "r"(b1));
}
__device__ __forceinline__ u32 w_half2(const float* __restrict__ W, int j, int k) {
    float2 f = *reinterpret_cast<const float2*>(W + j * HID + k);
    half2 h = __float22half2_rn(f);
    return *reinterpret_cast<u32*>(&h);
}

// no-op launch-slot shifter (keeps ncu's fixed sample index on k2)
__global__ void k_nop() {}

// ---------------------------------------------------------------------------
// K1: emb_proj[r][j] = sum_k emb[r][k]*W_ih[j][k] + (b_ih[j]+b_hh[j])
// ---------------------------------------------------------------------------
__global__ void __launch_bounds__(256) k1_embproj(
    const float* __restrict__ emb, const float* __restrict__ W_ih,
    const float* __restrict__ b_ih, const float* __restrict__ b_hh)
{
    __shared__ __align__(16) float es[80][52];
    const int j  = threadIdx.x;
    const int r0 = blockIdx.x * 80;

    u64 wk[26];
    {
        const float2* wr = reinterpret_cast<const float2*>(W_ih + j * 50);
#pragma unroll
        for (int m = 0; m < 25; m++) {
            float2 t = __ldg(&wr[m]);
            wk[m] = pack2(t.x, t.y);
        }
        wk[25] = 0ull;
    }
    const u64 biasp = pack2(b_ih[j] + b_hh[j], 0.0f);

    for (int idx = j; idx < 80 * 50; idx += 256)
        es[idx / 50][idx % 50] = emb[(r0 + idx / 50) * 50 + (idx % 50)];
    if (j < 160) es[j >> 1][50 + (j & 1)] = 0.0f;
    __syncthreads();

#pragma unroll 4
    for (int r = 0; r < 80; r++) {
        u64 acc = biasp;
#pragma unroll
        for (int m = 0; m < 13; m++) {
            ulonglong2 e2 = *reinterpret_cast<const ulonglong2*>(&es[r][m * 4]);
            fma2(acc, e2.x, wk[2 * m]);
            fma2(acc, e2.y, wk[2 * m + 1]);
        }
        float lo, hi; unpack2(acc, lo, hi);
        g_emb_proj[(r0 + r) * G4 + j] = lo + hi;
    }
}

// ---------------------------------------------------------------------------
// K2: LSTM recurrence via tensor cores (mma.sync m16n8k16 f16->f32).
// grid 256 CTAs x 256 threads, 4 batch rows per CTA, 2 CTAs/SM.
// M = 256 gate rows (16 m-tiles), N = 8 (batches 0-3 real, 4-7 zero), K = 64.
// Warp w owns m-tiles T1=w (gates i/f) and T2=w+8 (gates g/o); W_hh A-frags
// live in registers (fp16). h stored fp16 in smem, B-frag = 8 LDS.32/warp/step.
// ---------------------------------------------------------------------------
__global__ void __launch_bounds__(256, 2) k2_lstm(
    const int* __restrict__ x, const float* __restrict__ W_hh)
{
    __shared__ __half hS[8 * HSTRIDE];   // h fp16; rows 4..7 stay zero
    __shared__ float  gS[4][256];        // activated gates
    __shared__ float  gxS[4][256];       // gx for current step
    __shared__ int    xs[2][4];          // tokens for step t+1 (ping-pong)

    const int tid  = threadIdx.x;
    const int lane = tid & 31;
    const int w    = tid >> 5;           // warp 0..7
    const int g    = lane >> 2;          // 0..7
    const int t4   = lane & 3;           // 0..3
    const int b0   = blockIdx.x * 4;

    // ---- stationary A-fragments (W_hh fp16), tiles T1=w, T2=w+8 ----
    // PTX m16n8k16 A layout: a0={A[g][2t],A[g][2t+1]}, a1={A[g+8][...]},
    //                        a2={A[g][2t+8],...},      a3={A[g+8][2t+8],...}
    u32 A1[4][4], A2[4][4];
    {
        const int j1 = 16 * w + g;            // tile1 row (gates i/f)
        const int j2 = 16 * (w + 8) + g;      // tile2 row (gates g/o)
#pragma unroll
        for (int K = 0; K < 4; K++) {
            const int c = 16 * K + 2 * t4;
            A1[K][0] = w_half2(W_hh, j1,     c);
            A1[K][1] = w_half2(W_hh, j1 + 8, c);
            A1[K][2] = w_half2(W_hh, j1,     c + 8);
            A1[K][3] = w_half2(W_hh, j1 + 8, c + 8);
            A2[K][0] = w_half2(W_hh, j2,     c);
            A2[K][1] = w_half2(W_hh, j2 + 8, c);
            A2[K][2] = w_half2(W_hh, j2,     c + 8);
            A2[K][3] = w_half2(W_hh, j2 + 8, c + 8);
        }
    }

    // ---- prologue: zero h, gx(0) into gxS, xs[0] = tokens(step 1) ----
    for (int i = tid; i < 8 * HSTRIDE; i += 256) hS[i] = __float2half(0.0f);
    {
        int tok[4];
#pragma unroll
        for (int b = 0; b < 4; b++) tok[b] = x[(b0 + b) * SEQ];
#pragma unroll
        for (int b = 0; b < 4; b++)
            gxS[b][tid] = __ldg(g_emb_proj + (size_t)tok[b] * G4 + tid);
    }
    if (tid < 4) xs[0][tid] = x[(b0 + tid) * SEQ + 1];

    // update-phase ownership: b = tid>>6, k = tid&63
    const int ub = tid >> 6;
    const int uk = tid & 63;
    float c_st = 0.0f, h_st = 0.0f;

    __syncthreads();

    for (int t = 0; t < SEQ; t++) {
        // prefetch gx(t+1) using xs[t&1] (tokens for t+1)
        float gxn[4];
        {
            const int safe = (t + 1 < SEQ);
#pragma unroll
            for (int b = 0; b < 4; b++) {
                int tok = xs[t & 1][b];
                gxn[b] = safe ? __ldg(g_emb_proj + (size_t)tok * G4 + tid) : 0.0f;
            }
        }

        // ---- matvec via HMMA: D = W_hh(fp16) @ h(fp16), fp32 acc ----
        float d1[4] = {0.f, 0.f, 0.f, 0.f};
        float d2[4] = {0.f, 0.f, 0.f, 0.f};
#pragma unroll
        for (int K = 0; K < 4; K++) {
            const int kk = 16 * K + 2 * t4;
            u32 bb0 = *reinterpret_cast<const u32*>(&hS[g * HSTRIDE + kk]);
            u32 bb1 = *reinterpret_cast<const u32*>(&hS[g * HSTRIDE + kk + 8]);
            hmma16816(d1[0], d1[1], d1[2], d1[3],
                      A1[K][0], A1[K][1], A1[K][2], A1[K][3], bb0, bb1);
            hmma16816(d2[0], d2[1], d2[2], d2[3],
                      A2[K][0], A2[K][1], A2[K][2], A2[K][3], bb0, bb1);
        }

        // ---- epilogue: + gx, activation, store gates (real cols only) ----
        // D layout: d0=(row g, col 2t), d1=(g, 2t+1), d2=(g+8, 2t), d3=(g+8, 2t+1)
        if (t4 < 2) {
            const int bA = 2 * t4, bB = 2 * t4 + 1;
            const int j1a = 16 * w + g,        j1b = j1a + 8;       // sigmoid (i/f)
            const int j2a = 16 * (w + 8) + g,  j2b = j2a + 8;       // tanh if w<4 else sigmoid (g/o)
            float v;
            v = d1[0] + gxS[bA][j1a]; gS[bA][j1a] = sigmoid_(v);
            v = d1[1] + gxS[bB][j1a]; gS[bB][j1a] = sigmoid_(v);
            v = d1[2] + gxS[bA][j1b]; gS[bA][j1b] = sigmoid_(v);
            v = d1[3] + gxS[bB][j1b]; gS[bB][j1b] = sigmoid_(v);
            if (w < 4) {
                v = d2[0] + gxS[bA][j2a]; gS[bA][j2a] = tanh_(v);
                v = d2[1] + gxS[bB][j2a]; gS[bB][j2a] = tanh_(v);
                v = d2[2] + gxS[bA][j2b]; gS[bA][j2b] = tanh_(v);
                v = d2[3] + gxS[bB][j2b]; gS[bB][j2b] = tanh_(v);
            } else {
                v = d2[0] + gxS[bA][j2a]; gS[bA][j2a] = sigmoid_(v);
                v = d2[1] + gxS[bB][j2a]; gS[bB][j2a] = sigmoid_(v);
                v = d2[2] + gxS[bA][j2b]; gS[bA][j2b] = sigmoid_(v);
                v = d2[3] + gxS[bB][j2b]; gS[bB][j2b] = sigmoid_(v);
            }
        }
        __syncthreads();   // [B] gates visible

        // ---- update phase: c, h; also publish gx(t+1) + tokens(t+2) ----
        {
            float i_ = gS[ub][uk];
            float f_ = gS[ub][64 + uk];
            float g_ = gS[ub][128 + uk];
            float o_ = gS[ub][192 + uk];
            c_st = fmaf(f_, c_st, i_ * g_);
            h_st = o_ * tanh_(c_st);
            hS[ub * HSTRIDE + uk] = __float2half(h_st);
        }
#pragma unroll
        for (int b = 0; b < 4; b++) gxS[b][tid] = gxn[b];
        if (tid < 4) {
            int nt = t + 2 < SEQ ? t + 2 : SEQ - 1;
            xs[(t + 1) & 1][tid] = x[(b0 + tid) * SEQ + nt];
        }
        __syncthreads();   // [C] h + gx(t+1) visible
    }

    g_hfin[(b0 + ub) * HID + uk] = h_st;
}

// ---------------------------------------------------------------------------
// K3: out[b][c] = exp(h[b].W_fc[c] + b_fc[c]); per-CTA row partial sums
// ---------------------------------------------------------------------------
__global__ void __launch_bounds__(256) k3_fc(
    const float* __restrict__ W_fc, const float* __restrict__ b_fc,
    float* __restrict__ out)
{
    __shared__ __align__(16) float hS[16][64];
    __shared__ float ws[8][16];

    const int tid  = threadIdx.x;
    const int wid  = tid >> 5;
    const int lane = tid & 31;
    const int c    = blockIdx.x * 256 + tid;
    const bool valid = (c < NUM_CITIES);

    u64 wk[32];
    float bias = 0.0f;
    if (valid) {
        const ulonglong2* wr = reinterpret_cast<const ulonglong2*>(W_fc + c * HID);
#pragma unroll
        for (int q = 0; q < 16; q++) { ulonglong2 t = __ldg(&wr[q]); wk[2*q] = t.x; wk[2*q+1] = t.y; }
        bias = b_fc[c];
    } else {
#pragma unroll
        for (int q = 0; q < 32; q++) wk[q] = 0ull;
    }

    for (int bc = 0; bc < BATCH; bc += 16) {
        __syncthreads();
        reinterpret_cast<float4*>(hS)[tid] =
            reinterpret_cast<const float4*>(g_hfin + bc * HID)[tid];
        __syncthreads();

        u64 acc[16];
#pragma unroll
        for (int b = 0; b < 16; b++) acc[b] = 0ull;

#pragma unroll
        for (int q = 0; q < 16; q++) {
#pragma unroll
            for (int b = 0; b < 16; b++) {
                ulonglong2 hv = *reinterpret_cast<const ulonglong2*>(&hS[b][q * 4]);
                fma2(acc[b], hv.x, wk[2*q]);
                fma2(acc[b], hv.y, wk[2*q+1]);
            }
        }

#pragma unroll
        for (int b = 0; b < 16; b++) {
            float lo, hi;
            unpack2(acc[b], lo, hi);
            float l = lo + hi + bias;
            float e = fast_ex2(l * 1.4426950408889634f);
            float ev = valid ? e : 0.0f;
            if (valid) __stcs(&out[(size_t)(bc + b) * NUM_CITIES + c], e);
            ev += __shfl_xor_sync(0xffffffffu, ev, 16);
            ev += __shfl_xor_sync(0xffffffffu, ev, 8);
            ev += __shfl_xor_sync(0xffffffffu, ev, 4);
            ev += __shfl_xor_sync(0xffffffffu, ev, 2);
            ev += __shfl_xor_sync(0xffffffffu, ev, 1);
            if (lane == 0) ws[wid][b] = ev;
        }
        __syncthreads();

        if (tid < 16) {
            float s = 0.0f;
#pragma unroll
            for (int w = 0; w < 8; w++) s += ws[w][tid];
            g_partial[blockIdx.x * BATCH + bc + tid] = s;
        }
    }
}

// ---------------------------------------------------------------------------
// K3c: exact row-sum inverses. One warp per batch row.
// ---------------------------------------------------------------------------
__global__ void __launch_bounds__(128) k3c_inv()
{
    const int warp = (blockIdx.x * 128 + threadIdx.x) >> 5;   // 0..1023
    const int lane = threadIdx.x & 31;
    float s = 0.0f;
    for (int cta = lane; cta < K3_CTAS; cta += 32)
        s += g_partial[cta * BATCH + warp];
    s += __shfl_xor_sync(0xffffffffu, s, 16);
    s += __shfl_xor_sync(0xffffffffu, s, 8);
    s += __shfl_xor_sync(0xffffffffu, s, 4);
    s += __shfl_xor_sync(0xffffffffu, s, 2);
    s += __shfl_xor_sync(0xffffffffu, s, 1);
    if (lane == 0) g_rowinv[warp] = 1.0f / s;
}

// ---------------------------------------------------------------------------
// K4: pure streaming scale. One float4 per thread.
// ---------------------------------------------------------------------------
__global__ void __launch_bounds__(256) k4_scale(float4* __restrict__ out4)
{
    const int i = blockIdx.x * 256 + threadIdx.x;    // < 12,800,000
    const int b = i / (NUM_CITIES / 4);
    const float inv = g_rowinv[b];
    float4 v = __ldcs(&out4[i]);
    v.x *= inv; v.y *= inv; v.z *= inv; v.w *= inv;
    __stcs(&out4[i], v);
}

// ---------------------------------------------------------------------------
extern "C" void kernel_launch(void* const* d_in, const int* in_sizes, int n_in,
                              void* d_out, int out_size)
{
    (void)in_sizes; (void)n_in; (void)out_size;
    const int*   x    = (const int*)  d_in[0];
    const float* emb  = (const float*)d_in[1];
    const float* W_ih = (const float*)d_in[2];
    const float* W_hh = (const float*)d_in[3];
    const float* b_ih = (const float*)d_in[4];
    const float* b_hh = (const float*)d_in[5];
    const float* W_fc = (const float*)d_in[6];
    const float* b_fc = (const float*)d_in[7];
    float* out = (float*)d_out;

    k1_embproj<<<NUM_CITIES / 80, 256>>>(emb, W_ih, b_ih, b_hh);
    k_nop<<<1, 32>>>();
    k_nop<<<1, 32>>>();
    k2_lstm<<<BATCH / 4, 256>>>(x, W_hh);
    k3_fc<<<K3_CTAS, 256>>>(W_fc, b_fc, out);
    k3c_inv<<<256, 128>>>();
    k4_scale<<<(BATCH * NUM_CITIES / 4) / 256, 256>>>((float4*)out);
}

// round 7
// speedup vs baseline: 2.4395x; 1.6555x over previous
#include <cuda_runtime.h>
#include <cuda_fp16.h>
#include <cstdint>

typedef unsigned long long u64;
typedef unsigned int u32;

#define NUM_CITIES 50000
#define EMB 50
#define HID 64
#define G4 256          // 4 * HID
#define BATCH 1024
#define SEQ 512
#define K3_CTAS 196     // ceil(50000/256)
#define HSTRIDE 72      // fp16 h row stride (halfs)

// Scratch (no allocation allowed -> device globals)
__device__ float g_emb_proj[NUM_CITIES * G4];     // emb @ W_ih^T + bias, 51.2MB
__device__ float g_hfin[BATCH * HID];             // final hidden state
__device__ float g_partial[K3_CTAS * BATCH];      // per-CTA row partial sums
__device__ float g_rowinv[BATCH];                 // 1/rowsum

// ---------------------------------------------------------------------------
// helpers
// ---------------------------------------------------------------------------
__device__ __forceinline__ float fast_ex2(float x) {
    float r; asm("ex2.approx.f32 %0, %1;" : "=f"(r) : "f"(x)); return r;
}
__device__ __forceinline__ float fast_rcp(float x) {
    float r; asm("rcp.approx.f32 %0, %1;" : "=f"(r) : "f"(x)); return r;
}
__device__ __forceinline__ float tanh_t(float x) {        // 1 MUFU op
    float r; asm("tanh.approx.f32 %0, %1;" : "=f"(r) : "f"(x)); return r;
}
__device__ __forceinline__ float sig_t(float x) {         // 1 MUFU + 1 FMA
    return fmaf(0.5f, tanh_t(0.5f * x), 0.5f);
}
__device__ __forceinline__ float sigmoid_(float x) {      // accurate (k-epilogue unused paths)
    return fast_rcp(1.0f + fast_ex2(-1.4426950408889634f * x));
}
__device__ __forceinline__ void unpack2(u64 v, float& lo, float& hi) {
    asm("mov.b64 {%0,%1}, %2;" : "=f"(lo), "=f"(hi) : "l"(v));
}
__device__ __forceinline__ u64 pack2(float lo, float hi) {
    u64 v; asm("mov.b64 %0, {%1,%2};" : "=l"(v) : "f"(lo), "f"(hi)); return v;
}
__device__ __forceinline__ void fma2(u64& acc, u64 a, u64 b) {
    asm("fma.rn.f32x2 %0, %1, %2, %0;" : "+l"(acc) : "l"(a), "l"(b));
}
__device__ __forceinline__ void hmma16816(
    float& d0, float& d1, float& d2, float& d3,
    u32 a0, u32 a1, u32 a2, u32 a3, u32 b0, u32 b1)
{
    asm("mma.sync.aligned.m16n8k16.row.col.f32.f16.f16.f32 "
        "{%0,%1,%2,%3}, {%4,%5,%6,%7}, {%8,%9}, {%0,%1,%2,%3};"
        : "+f"(d0), "+f"(d1), "+f"(d2), "+f"(d3)
        : "r"(a0), "r"(a1), "r"(a2), "r"(a3), "r"(b0), "r"(b1));
}
__device__ __forceinline__ u32 w_half2(const float* __restrict__ W, int j, int k) {
    float2 f = *reinterpret_cast<const float2*>(W + j * HID + k);
    half2 h = __float22half2_rn(f);
    return *reinterpret_cast<u32*>(&h);
}

// no-op launch-slot shifters (keep ncu's fixed sample index on k2)
__global__ void k_nop() {}

// ---------------------------------------------------------------------------
// K1: emb_proj[r][j] = sum_k emb[r][k]*W_ih[j][k] + (b_ih[j]+b_hh[j])
// ---------------------------------------------------------------------------
__global__ void __launch_bounds__(256) k1_embproj(
    const float* __restrict__ emb, const float* __restrict__ W_ih,
    const float* __restrict__ b_ih, const float* __restrict__ b_hh)
{
    __shared__ __align__(16) float es[80][52];
    const int j  = threadIdx.x;
    const int r0 = blockIdx.x * 80;

    u64 wk[26];
    {
        const float2* wr = reinterpret_cast<const float2*>(W_ih + j * 50);
#pragma unroll
        for (int m = 0; m < 25; m++) {
            float2 t = __ldg(&wr[m]);
            wk[m] = pack2(t.x, t.y);
        }
        wk[25] = 0ull;
    }
    const u64 biasp = pack2(b_ih[j] + b_hh[j], 0.0f);

    for (int idx = j; idx < 80 * 50; idx += 256)
        es[idx / 50][idx % 50] = emb[(r0 + idx / 50) * 50 + (idx % 50)];
    if (j < 160) es[j >> 1][50 + (j & 1)] = 0.0f;
    __syncthreads();

#pragma unroll 4
    for (int r = 0; r < 80; r++) {
        u64 acc = biasp;
#pragma unroll
        for (int m = 0; m < 13; m++) {
            ulonglong2 e2 = *reinterpret_cast<const ulonglong2*>(&es[r][m * 4]);
            fma2(acc, e2.x, wk[2 * m]);
            fma2(acc, e2.y, wk[2 * m + 1]);
        }
        float lo, hi; unpack2(acc, lo, hi);
        g_emb_proj[(r0 + r) * G4 + j] = lo + hi;
    }
}

// ---------------------------------------------------------------------------
// K2: LSTM recurrence, gate-aligned HMMA tiling, ONE barrier per step.
// grid 256 CTAs x 128 threads (4 warps), 4 batch rows per CTA.
// Warp w owns k-slice [16w,16w+16) of ALL FOUR gates: 4 m-tiles x 4 K-steps
// = 16 HMMA/step with W_hh stationary in registers (fp16).
// After an intra-warp shfl rebalance each lane holds i,f,g,o for its
// (kc, 2 batches) -> c/h update is register-local. h double-buffered fp16.
// Activations use tanh.approx (1 MUFU each).
// ---------------------------------------------------------------------------
__global__ void __launch_bounds__(128, 2) k2_lstm(
    const int* __restrict__ x, const float* __restrict__ W_hh)
{
    __shared__ __align__(16) __half hS[2][8 * HSTRIDE];  // [buf][batchRow*HSTRIDE + k]
    __shared__ int xs[2][4];                             // tokens for step t+1

    const int tid  = threadIdx.x;
    const int lane = tid & 31;
    const int w    = tid >> 5;          // warp 0..3
    const int g    = lane >> 2;         // 0..7
    const int t4   = lane & 3;          // 0..3
    const int b0   = blockIdx.x * 4;

    // lane ownership for update phase
    const int kc = 16 * w + g + ((t4 >> 1) ? 8 : 0);   // k column 0..63
    const int bA = (t4 & 1) * 2;                        // batches bA, bA+1
    const int bB = bA + 1;

    // ---- stationary A-fragments: gate G tile rows j = 64G + 16w + g(+8) ----
    u32 A[4][4][4];   // [gate][Kstep][frag]
#pragma unroll
    for (int G = 0; G < 4; G++) {
        const int j = 64 * G + 16 * w + g;
#pragma unroll
        for (int K = 0; K < 4; K++) {
            const int c = 16 * K + 2 * t4;
            A[G][K][0] = w_half2(W_hh, j,     c);
            A[G][K][1] = w_half2(W_hh, j + 8, c);
            A[G][K][2] = w_half2(W_hh, j,     c + 8);
            A[G][K][3] = w_half2(W_hh, j + 8, c + 8);
        }
    }

    // ---- prologue: zero h buffers; gx(0) into regs; xs[0] = tokens(t=1) ----
    {
        __half* hz = &hS[0][0];
        for (int i = tid; i < 2 * 8 * HSTRIDE; i += 128) hz[i] = __float2half(0.0f);
    }
    float gxA[4], gxB[4];
    {
        const int tokA = __ldg(&x[(b0 + bA) * SEQ]);
        const int tokB = __ldg(&x[(b0 + bB) * SEQ]);
#pragma unroll
        for (int G = 0; G < 4; G++) {
            gxA[G] = __ldg(g_emb_proj + (size_t)tokA * G4 + 64 * G + kc);
            gxB[G] = __ldg(g_emb_proj + (size_t)tokB * G4 + 64 * G + kc);
        }
    }
    if (tid < 4) xs[0][tid] = x[(b0 + tid) * SEQ + 1];

    float cA = 0.0f, cB = 0.0f, hA = 0.0f, hB = 0.0f;

    __syncthreads();

    for (int t = 0; t < SEQ; t++) {
        const int buf = t & 1;
        const __half* hb = hS[buf];

        // ---- 16 HMMA: all 4 gates for this warp's k-slice ----
        float D[4][4];
#pragma unroll
        for (int G = 0; G < 4; G++) {
            D[G][0] = 0.f; D[G][1] = 0.f; D[G][2] = 0.f; D[G][3] = 0.f;
        }
#pragma unroll
        for (int K = 0; K < 4; K++) {
            const int kk = 16 * K + 2 * t4;
            u32 bb0 = *reinterpret_cast<const u32*>(&hb[g * HSTRIDE + kk]);
            u32 bb1 = *reinterpret_cast<const u32*>(&hb[g * HSTRIDE + kk + 8]);
#pragma unroll
            for (int G = 0; G < 4; G++)
                hmma16816(D[G][0], D[G][1], D[G][2], D[G][3],
                          A[G][K][0], A[G][K][1], A[G][K][2], A[G][K][3], bb0, bb1);
        }

        // ---- prefetch gx(t+1) (L2-resident; consumed next step) ----
        float nA[4] = {0.f,0.f,0.f,0.f}, nB[4] = {0.f,0.f,0.f,0.f};
        if (t + 1 < SEQ) {
            const int tokA = xs[buf][bA];
            const int tokB = xs[buf][bB];
#pragma unroll
            for (int G = 0; G < 4; G++) {
                nA[G] = __ldg(g_emb_proj + (size_t)tokA * G4 + 64 * G + kc);
                nB[G] = __ldg(g_emb_proj + (size_t)tokB * G4 + 64 * G + kc);
            }
        }

        // ---- shfl rebalance: lanes t4>=2 take the (g+8) rows ----
        float xA[4], xB[4];
#pragma unroll
        for (int G = 0; G < 4; G++) {
            float sA = __shfl_xor_sync(0xffffffffu, D[G][2], 2);
            float sB = __shfl_xor_sync(0xffffffffu, D[G][3], 2);
            xA[G] = ((t4 < 2) ? D[G][0] : sA) + gxA[G];
            xB[G] = ((t4 < 2) ? D[G][1] : sB) + gxB[G];
        }

        // ---- register-local LSTM update for (kc, bA) and (kc, bB) ----
        {
            float i_ = sig_t(xA[0]), f_ = sig_t(xA[1]);
            float g_ = tanh_t(xA[2]), o_ = sig_t(xA[3]);
            cA = fmaf(f_, cA, i_ * g_);
            hA = o_ * tanh_t(cA);
        }
        {
            float i_ = sig_t(xB[0]), f_ = sig_t(xB[1]);
            float g_ = tanh_t(xB[2]), o_ = sig_t(xB[3]);
            cB = fmaf(f_, cB, i_ * g_);
            hB = o_ * tanh_t(cB);
        }

        // ---- publish h(t+1), tokens(t+2), roll gx regs ----
        {
            __half* hn = hS[buf ^ 1];
            hn[bA * HSTRIDE + kc] = __float2half(hA);
            hn[bB * HSTRIDE + kc] = __float2half(hB);
        }
        if (tid < 4) {
            int nt = (t + 2 < SEQ) ? (t + 2) : (SEQ - 1);
            xs[buf ^ 1][tid] = x[(b0 + tid) * SEQ + nt];
        }
#pragma unroll
        for (int G = 0; G < 4; G++) { gxA[G] = nA[G]; gxB[G] = nB[G]; }

        __syncthreads();
    }

    g_hfin[(b0 + bA) * HID + kc] = hA;
    g_hfin[(b0 + bB) * HID + kc] = hB;
}

// ---------------------------------------------------------------------------
// K3: out[b][c] = exp(h[b].W_fc[c] + b_fc[c]); per-CTA row partial sums.
// grid (196, 4): x = city block, y = batch quarter (256 rows) for wave balance.
// ---------------------------------------------------------------------------
__global__ void __launch_bounds__(256) k3_fc(
    const float* __restrict__ W_fc, const float* __restrict__ b_fc,
    float* __restrict__ out)
{
    __shared__ __align__(16) float hS[16][64];
    __shared__ float ws[8][16];

    const int tid  = threadIdx.x;
    const int wid  = tid >> 5;
    const int lane = tid & 31;
    const int c    = blockIdx.x * 256 + tid;
    const int bq   = blockIdx.y * 256;          // batch quarter base
    const bool valid = (c < NUM_CITIES);

    u64 wk[32];
    float bias = 0.0f;
    if (valid) {
        const ulonglong2* wr = reinterpret_cast<const ulonglong2*>(W_fc + c * HID);
#pragma unroll
        for (int q = 0; q < 16; q++) { ulonglong2 t = __ldg(&wr[q]); wk[2*q] = t.x; wk[2*q+1] = t.y; }
        bias = b_fc[c];
    } else {
#pragma unroll
        for (int q = 0; q < 32; q++) wk[q] = 0ull;
    }

    for (int bc = bq; bc < bq + 256; bc += 16) {
        __syncthreads();
        reinterpret_cast<float4*>(hS)[tid] =
            reinterpret_cast<const float4*>(g_hfin + bc * HID)[tid];
        __syncthreads();

        u64 acc[16];
#pragma unroll
        for (int b = 0; b < 16; b++) acc[b] = 0ull;

#pragma unroll
        for (int q = 0; q < 16; q++) {
#pragma unroll
            for (int b = 0; b < 16; b++) {
                ulonglong2 hv = *reinterpret_cast<const ulonglong2*>(&hS[b][q * 4]);
                fma2(acc[b], hv.x, wk[2*q]);
                fma2(acc[b], hv.y, wk[2*q+1]);
            }
        }

#pragma unroll
        for (int b = 0; b < 16; b++) {
            float lo, hi;
            unpack2(acc[b], lo, hi);
            float l = lo + hi + bias;
            float e = fast_ex2(l * 1.4426950408889634f);
            float ev = valid ? e : 0.0f;
            if (valid) __stcs(&out[(size_t)(bc + b) * NUM_CITIES + c], e);
            ev += __shfl_xor_sync(0xffffffffu, ev, 16);
            ev += __shfl_xor_sync(0xffffffffu, ev, 8);
            ev += __shfl_xor_sync(0xffffffffu, ev, 4);
            ev += __shfl_xor_sync(0xffffffffu, ev, 2);
            ev += __shfl_xor_sync(0xffffffffu, ev, 1);
            if (lane == 0) ws[wid][b] = ev;
        }
        __syncthreads();

        if (tid < 16) {
            float s = 0.0f;
#pragma unroll
            for (int w = 0; w < 8; w++) s += ws[w][tid];
            g_partial[blockIdx.x * BATCH + bc + tid] = s;
        }
    }
}

// ---------------------------------------------------------------------------
// K3c: exact row-sum inverses. One warp per batch row.
// ---------------------------------------------------------------------------
__global__ void __launch_bounds__(128) k3c_inv()
{
    const int warp = (blockIdx.x * 128 + threadIdx.x) >> 5;   // 0..1023
    const int lane = threadIdx.x & 31;
    float s = 0.0f;
    for (int cta = lane; cta < K3_CTAS; cta += 32)
        s += g_partial[cta * BATCH + warp];
    s += __shfl_xor_sync(0xffffffffu, s, 16);
    s += __shfl_xor_sync(0xffffffffu, s, 8);
    s += __shfl_xor_sync(0xffffffffu, s, 4);
    s += __shfl_xor_sync(0xffffffffu, s, 2);
    s += __shfl_xor_sync(0xffffffffu, s, 1);
    if (lane == 0) g_rowinv[warp] = 1.0f / s;
}

// ---------------------------------------------------------------------------
// K4: pure streaming scale. One float4 per thread.
// ---------------------------------------------------------------------------
__global__ void __launch_bounds__(256) k4_scale(float4* __restrict__ out4)
{
    const int i = blockIdx.x * 256 + threadIdx.x;    // < 12,800,000
    const int b = i / (NUM_CITIES / 4);
    const float inv = g_rowinv[b];
    float4 v = __ldcs(&out4[i]);
    v.x *= inv; v.y *= inv; v.z *= inv; v.w *= inv;
    __stcs(&out4[i], v);
}

// ---------------------------------------------------------------------------
extern "C" void kernel_launch(void* const* d_in, const int* in_sizes, int n_in,
                              void* d_out, int out_size)
{
    (void)in_sizes; (void)n_in; (void)out_size;
    const int*   x    = (const int*)  d_in[0];
    const float* emb  = (const float*)d_in[1];
    const float* W_ih = (const float*)d_in[2];
    const float* W_hh = (const float*)d_in[3];
    const float* b_ih = (const float*)d_in[4];
    const float* b_hh = (const float*)d_in[5];
    const float* W_fc = (const float*)d_in[6];
    const float* b_fc = (const float*)d_in[7];
    float* out = (float*)d_out;

    k1_embproj<<<NUM_CITIES / 80, 256>>>(emb, W_ih, b_ih, b_hh);
    k_nop<<<1, 32>>>();
    k_nop<<<1, 32>>>();
    k2_lstm<<<BATCH / 4, 128>>>(x, W_hh);
    dim3 g3(K3_CTAS, 4);
    k3_fc<<<g3, 256>>>(W_fc, b_fc, out);
    k3c_inv<<<256, 128>>>();
    k4_scale<<<(BATCH * NUM_CITIES / 4) / 256, 256>>>((float4*)out);
}

// round 8
// speedup vs baseline: 3.7536x; 1.5387x over previous
#include <cuda_runtime.h>
#include <cuda_fp16.h>
#include <cstdint>

typedef unsigned long long u64;
typedef unsigned int u32;

#define NUM_CITIES 50000
#define EMB 50
#define HID 64
#define G4 256          // 4 * HID
#define BATCH 1024
#define SEQ 512
#define K3_CTAS 391     // ceil(50000/128)
#define HSTRIDE 72      // fp16 h row stride (halfs)

// Scratch (no allocation allowed -> device globals)
__device__ float g_emb_proj[NUM_CITIES * G4];     // emb @ W_ih^T + bias, 51.2MB
__device__ float g_hfin[BATCH * HID];             // final hidden state
__device__ float g_partial[K3_CTAS * BATCH];      // per-CTA row partial sums
__device__ float g_rowinv[BATCH];                 // 1/rowsum

// ---------------------------------------------------------------------------
// helpers
// ---------------------------------------------------------------------------
__device__ __forceinline__ float fast_ex2(float x) {
    float r; asm("ex2.approx.f32 %0, %1;" : "=f"(r) : "f"(x)); return r;
}
__device__ __forceinline__ float tanh_t(float x) {        // 1 MUFU op
    float r; asm("tanh.approx.f32 %0, %1;" : "=f"(r) : "f"(x)); return r;
}
__device__ __forceinline__ float sig_t(float x) {         // 1 MUFU + 1 FMA
    return fmaf(0.5f, tanh_t(0.5f * x), 0.5f);
}
__device__ __forceinline__ void unpack2(u64 v, float& lo, float& hi) {
    asm("mov.b64 {%0,%1}, %2;" : "=f"(lo), "=f"(hi) : "l"(v));
}
__device__ __forceinline__ u64 pack2(float lo, float hi) {
    u64 v; asm("mov.b64 %0, {%1,%2};" : "=l"(v) : "f"(lo), "f"(hi)); return v;
}
__device__ __forceinline__ void fma2(u64& acc, u64 a, u64 b) {
    asm("fma.rn.f32x2 %0, %1, %2, %0;" : "+l"(acc) : "l"(a), "l"(b));
}
__device__ __forceinline__ void hmma16816(
    float& d0, float& d1, float& d2, float& d3,
    u32 a0, u32 a1, u32 a2, u32 a3, u32 b0, u32 b1)
{
    asm("mma.sync.aligned.m16n8k16.row.col.f32.f16.f16.f32 "
        "{%0,%1,%2,%3}, {%4,%5,%6,%7}, {%8,%9}, {%0,%1,%2,%3};"
        : "+f"(d0), "+f"(d1), "+f"(d2), "+f"(d3)
        : "r"(a0), "r"(a1), "r"(a2), "r"(a3), "r"(b0), "r"(b1));
}
__device__ __forceinline__ u32 w_half2(const float* __restrict__ W, int j, int k) {
    float2 f = *reinterpret_cast<const float2*>(W + j * HID + k);
    half2 h = __float22half2_rn(f);
    return *reinterpret_cast<u32*>(&h);
}

// no-op launch-slot shifter (keeps ncu's fixed sample index on k3 this round)
__global__ void k_nop() {}

// ---------------------------------------------------------------------------
// K1: emb_proj[r][j] = sum_k emb[r][k]*W_ih[j][k] + (b_ih[j]+b_hh[j])
// ---------------------------------------------------------------------------
__global__ void __launch_bounds__(256) k1_embproj(
    const float* __restrict__ emb, const float* __restrict__ W_ih,
    const float* __restrict__ b_ih, const float* __restrict__ b_hh)
{
    __shared__ __align__(16) float es[80][52];
    const int j  = threadIdx.x;
    const int r0 = blockIdx.x * 80;

    u64 wk[26];
    {
        const float2* wr = reinterpret_cast<const float2*>(W_ih + j * 50);
#pragma unroll
        for (int m = 0; m < 25; m++) {
            float2 t = __ldg(&wr[m]);
            wk[m] = pack2(t.x, t.y);
        }
        wk[25] = 0ull;
    }
    const u64 biasp = pack2(b_ih[j] + b_hh[j], 0.0f);

    for (int idx = j; idx < 80 * 50; idx += 256)
        es[idx / 50][idx % 50] = emb[(r0 + idx / 50) * 50 + (idx % 50)];
    if (j < 160) es[j >> 1][50 + (j & 1)] = 0.0f;
    __syncthreads();

#pragma unroll 4
    for (int r = 0; r < 80; r++) {
        u64 acc = biasp;
#pragma unroll
        for (int m = 0; m < 13; m++) {
            ulonglong2 e2 = *reinterpret_cast<const ulonglong2*>(&es[r][m * 4]);
            fma2(acc, e2.x, wk[2 * m]);
            fma2(acc, e2.y, wk[2 * m + 1]);
        }
        float lo, hi; unpack2(acc, lo, hi);
        g_emb_proj[(r0 + r) * G4 + j] = lo + hi;
    }
}

// ---------------------------------------------------------------------------
// K2: LSTM recurrence, gate-aligned HMMA tiling, ONE barrier per step.
// (unchanged from R7 — measured 218us)
// ---------------------------------------------------------------------------
__global__ void __launch_bounds__(128, 2) k2_lstm(
    const int* __restrict__ x, const float* __restrict__ W_hh)
{
    __shared__ __align__(16) __half hS[2][8 * HSTRIDE];
    __shared__ int xs[2][4];

    const int tid  = threadIdx.x;
    const int lane = tid & 31;
    const int w    = tid >> 5;
    const int g    = lane >> 2;
    const int t4   = lane & 3;
    const int b0   = blockIdx.x * 4;

    const int kc = 16 * w + g + ((t4 >> 1) ? 8 : 0);
    const int bA = (t4 & 1) * 2;
    const int bB = bA + 1;

    u32 A[4][4][4];
#pragma unroll
    for (int G = 0; G < 4; G++) {
        const int j = 64 * G + 16 * w + g;
#pragma unroll
        for (int K = 0; K < 4; K++) {
            const int c = 16 * K + 2 * t4;
            A[G][K][0] = w_half2(W_hh, j,     c);
            A[G][K][1] = w_half2(W_hh, j + 8, c);
            A[G][K][2] = w_half2(W_hh, j,     c + 8);
            A[G][K][3] = w_half2(W_hh, j + 8, c + 8);
        }
    }

    {
        __half* hz = &hS[0][0];
        for (int i = tid; i < 2 * 8 * HSTRIDE; i += 128) hz[i] = __float2half(0.0f);
    }
    float gxA[4], gxB[4];
    {
        const int tokA = __ldg(&x[(b0 + bA) * SEQ]);
        const int tokB = __ldg(&x[(b0 + bB) * SEQ]);
#pragma unroll
        for (int G = 0; G < 4; G++) {
            gxA[G] = __ldg(g_emb_proj + (size_t)tokA * G4 + 64 * G + kc);
            gxB[G] = __ldg(g_emb_proj + (size_t)tokB * G4 + 64 * G + kc);
        }
    }
    if (tid < 4) xs[0][tid] = x[(b0 + tid) * SEQ + 1];

    float cA = 0.0f, cB = 0.0f, hA = 0.0f, hB = 0.0f;

    __syncthreads();

    for (int t = 0; t < SEQ; t++) {
        const int buf = t & 1;
        const __half* hb = hS[buf];

        float D[4][4];
#pragma unroll
        for (int G = 0; G < 4; G++) {
            D[G][0] = 0.f; D[G][1] = 0.f; D[G][2] = 0.f; D[G][3] = 0.f;
        }
#pragma unroll
        for (int K = 0; K < 4; K++) {
            const int kk = 16 * K + 2 * t4;
            u32 bb0 = *reinterpret_cast<const u32*>(&hb[g * HSTRIDE + kk]);
            u32 bb1 = *reinterpret_cast<const u32*>(&hb[g * HSTRIDE + kk + 8]);
#pragma unroll
            for (int G = 0; G < 4; G++)
                hmma16816(D[G][0], D[G][1], D[G][2], D[G][3],
                          A[G][K][0], A[G][K][1], A[G][K][2], A[G][K][3], bb0, bb1);
        }

        float nA[4] = {0.f,0.f,0.f,0.f}, nB[4] = {0.f,0.f,0.f,0.f};
        if (t + 1 < SEQ) {
            const int tokA = xs[buf][bA];
            const int tokB = xs[buf][bB];
#pragma unroll
            for (int G = 0; G < 4; G++) {
                nA[G] = __ldg(g_emb_proj + (size_t)tokA * G4 + 64 * G + kc);
                nB[G] = __ldg(g_emb_proj + (size_t)tokB * G4 + 64 * G + kc);
            }
        }

        float xA[4], xB[4];
#pragma unroll
        for (int G = 0; G < 4; G++) {
            float sA = __shfl_xor_sync(0xffffffffu, D[G][2], 2);
            float sB = __shfl_xor_sync(0xffffffffu, D[G][3], 2);
            xA[G] = ((t4 < 2) ? D[G][0] : sA) + gxA[G];
            xB[G] = ((t4 < 2) ? D[G][1] : sB) + gxB[G];
        }

        {
            float i_ = sig_t(xA[0]), f_ = sig_t(xA[1]);
            float g_ = tanh_t(xA[2]), o_ = sig_t(xA[3]);
            cA = fmaf(f_, cA, i_ * g_);
            hA = o_ * tanh_t(cA);
        }
        {
            float i_ = sig_t(xB[0]), f_ = sig_t(xB[1]);
            float g_ = tanh_t(xB[2]), o_ = sig_t(xB[3]);
            cB = fmaf(f_, cB, i_ * g_);
            hB = o_ * tanh_t(cB);
        }

        {
            __half* hn = hS[buf ^ 1];
            hn[bA * HSTRIDE + kc] = __float2half(hA);
            hn[bB * HSTRIDE + kc] = __float2half(hB);
        }
        if (tid < 4) {
            int nt = (t + 2 < SEQ) ? (t + 2) : (SEQ - 1);
            xs[buf ^ 1][tid] = x[(b0 + tid) * SEQ + nt];
        }
#pragma unroll
        for (int G = 0; G < 4; G++) { gxA[G] = nA[G]; gxB[G] = nB[G]; }

        __syncthreads();
    }

    g_hfin[(b0 + bA) * HID + kc] = hA;
    g_hfin[(b0 + bB) * HID + kc] = hB;
}

// ---------------------------------------------------------------------------
// K3: tensor-core FC. out[b][c] = exp(h[b].W_fc[c] + b_fc[c]).
// grid 391 CTAs x 256 threads. CTA = 128 cities (warp = 16-city m-tile,
// W_fc A-frags stationary fp16). Loop: 16 chunks of 64 batches; h staged
// fp16 in smem; 8 n-tiles of 8 batches each => 4 HMMA per n-tile.
// Deterministic per-CTA batch partial sums via shfl + smem (no atomics).
// ---------------------------------------------------------------------------
__global__ void __launch_bounds__(256) k3_fc(
    const float* __restrict__ W_fc, const float* __restrict__ b_fc,
    float* __restrict__ out)
{
    __shared__ __align__(16) __half hs[64 * HSTRIDE];   // h chunk fp16 [64][72]
    __shared__ float ws[8][64];                          // per-warp batch partials

    const int tid  = threadIdx.x;
    const int lane = tid & 31;
    const int w    = tid >> 5;          // warp 0..7
    const int g    = lane >> 2;         // 0..7
    const int t4   = lane & 3;          // 0..3

    const int cb   = blockIdx.x * 128;
    const int j1   = cb + 16 * w + g;       // lane's city row A (a0/a2)
    const int j2   = j1 + 8;                // lane's city row B (a1/a3)
    const bool v1  = (j1 < NUM_CITIES);
    const bool v2  = (j2 < NUM_CITIES);

    // stationary A-fragments: W_fc rows j1/j2, fp16
    u32 A[4][4];
#pragma unroll
    for (int K = 0; K < 4; K++) {
        const int c = 16 * K + 2 * t4;
        A[K][0] = v1 ? w_half2(W_fc, j1, c)     : 0u;
        A[K][1] = v2 ? w_half2(W_fc, j2, c)     : 0u;
        A[K][2] = v1 ? w_half2(W_fc, j1, c + 8) : 0u;
        A[K][3] = v2 ? w_half2(W_fc, j2, c + 8) : 0u;
    }
    const float bias1 = v1 ? __ldg(&b_fc[j1]) : 0.0f;
    const float bias2 = v2 ? __ldg(&b_fc[j2]) : 0.0f;

    for (int chunk = 0; chunk < 16; chunk++) {
        const int cb64 = chunk * 64;
        __syncthreads();   // hs/ws reusable
        // stage h chunk: 64 batches x 64 hid, fp32 -> fp16
        for (int i = tid; i < 64 * 32; i += 256) {
            const int r = i >> 5;          // batch row 0..63
            const int cp = i & 31;         // float2 index 0..31
            float2 v = *reinterpret_cast<const float2*>(
                g_hfin + (cb64 + r) * HID + 2 * cp);
            half2 h = __float22half2_rn(v);
            *reinterpret_cast<u32*>(&hs[r * HSTRIDE + 2 * cp]) =
                *reinterpret_cast<u32*>(&h);
        }
        __syncthreads();

#pragma unroll
        for (int nt = 0; nt < 8; nt++) {
            const int nb = cb64 + nt * 8;
            float d0 = 0.f, d1 = 0.f, d2 = 0.f, d3 = 0.f;
#pragma unroll
            for (int K = 0; K < 4; K++) {
                const int kk = 16 * K + 2 * t4;
                const __half* hrow = &hs[(nt * 8 + g) * HSTRIDE];
                u32 bb0 = *reinterpret_cast<const u32*>(&hrow[kk]);
                u32 bb1 = *reinterpret_cast<const u32*>(&hrow[kk + 8]);
                hmma16816(d0, d1, d2, d3, A[K][0], A[K][1], A[K][2], A[K][3], bb0, bb1);
            }
            // epilogue: D layout d0=(j1, nb+2t4) d1=(j1, nb+2t4+1)
            //                     d2=(j2, nb+2t4) d3=(j2, nb+2t4+1)
            const float LOG2E = 1.4426950408889634f;
            float e0 = v1 ? fast_ex2((d0 + bias1) * LOG2E) : 0.0f;
            float e1 = v1 ? fast_ex2((d1 + bias1) * LOG2E) : 0.0f;
            float e2 = v2 ? fast_ex2((d2 + bias2) * LOG2E) : 0.0f;
            float e3 = v2 ? fast_ex2((d3 + bias2) * LOG2E) : 0.0f;
            const size_t rA = (size_t)(nb + 2 * t4) * NUM_CITIES;
            const size_t rB = (size_t)(nb + 2 * t4 + 1) * NUM_CITIES;
            if (v1) { __stcs(&out[rA + j1], e0); __stcs(&out[rB + j1], e1); }
            if (v2) { __stcs(&out[rA + j2], e2); __stcs(&out[rB + j2], e3); }

            // batch partial sums over this warp's 16 cities
            float s0 = e0 + e2;   // col nb+2t4
            float s1 = e1 + e3;   // col nb+2t4+1
#pragma unroll
            for (int m = 4; m <= 16; m <<= 1) {
                s0 += __shfl_xor_sync(0xffffffffu, s0, m);
                s1 += __shfl_xor_sync(0xffffffffu, s1, m);
            }
            if (g == 0) {
                ws[w][nt * 8 + 2 * t4]     = s0;
                ws[w][nt * 8 + 2 * t4 + 1] = s1;
            }
        }
        __syncthreads();
        if (tid < 64) {
            float s = 0.0f;
#pragma unroll
            for (int ww = 0; ww < 8; ww++) s += ws[ww][tid];
            g_partial[blockIdx.x * BATCH + cb64 + tid] = s;
        }
    }
}

// ---------------------------------------------------------------------------
// K3c: exact row-sum inverses. One warp per batch row.
// ---------------------------------------------------------------------------
__global__ void __launch_bounds__(128) k3c_inv()
{
    const int warp = (blockIdx.x * 128 + threadIdx.x) >> 5;   // 0..1023
    const int lane = threadIdx.x & 31;
    float s = 0.0f;
    for (int cta = lane; cta < K3_CTAS; cta += 32)
        s += g_partial[cta * BATCH + warp];
    s += __shfl_xor_sync(0xffffffffu, s, 16);
    s += __shfl_xor_sync(0xffffffffu, s, 8);
    s += __shfl_xor_sync(0xffffffffu, s, 4);
    s += __shfl_xor_sync(0xffffffffu, s, 2);
    s += __shfl_xor_sync(0xffffffffu, s, 1);
    if (lane == 0) g_rowinv[warp] = 1.0f / s;
}

// ---------------------------------------------------------------------------
// K4: pure streaming scale. One float4 per thread.
// ---------------------------------------------------------------------------
__global__ void __launch_bounds__(256) k4_scale(float4* __restrict__ out4)
{
    const int i = blockIdx.x * 256 + threadIdx.x;    // < 12,800,000
    const int b = i / (NUM_CITIES / 4);
    const float inv = g_rowinv[b];
    float4 v = __ldcs(&out4[i]);
    v.x *= inv; v.y *= inv; v.z *= inv; v.w *= inv;
    __stcs(&out4[i], v);
}

// ---------------------------------------------------------------------------
extern "C" void kernel_launch(void* const* d_in, const int* in_sizes, int n_in,
                              void* d_out, int out_size)
{
    (void)in_sizes; (void)n_in; (void)out_size;
    const int*   x    = (const int*)  d_in[0];
    const float* emb  = (const float*)d_in[1];
    const float* W_ih = (const float*)d_in[2];
    const float* W_hh = (const float*)d_in[3];
    const float* b_ih = (const float*)d_in[4];
    const float* b_hh = (const float*)d_in[5];
    const float* W_fc = (const float*)d_in[6];
    const float* b_fc = (const float*)d_in[7];
    float* out = (float*)d_out;

    k1_embproj<<<NUM_CITIES / 80, 256>>>(emb, W_ih, b_ih, b_hh);
    k2_lstm<<<BATCH / 4, 128>>>(x, W_hh);
    k_nop<<<1, 32>>>();
    k3_fc<<<K3_CTAS, 256>>>(W_fc, b_fc, out);      // launch idx 3 -> profiled
    k3c_inv<<<256, 128>>>();
    k4_scale<<<(BATCH * NUM_CITIES / 4) / 256, 256>>>((float4*)out);
}

// round 9
// speedup vs baseline: 3.8996x; 1.0389x over previous
#include <cuda_runtime.h>
#include <cuda_fp16.h>
#include <cstdint>

typedef unsigned long long u64;
typedef unsigned int u32;
typedef unsigned short u16;

#define NUM_CITIES 50000
#define EMB 50
#define HID 64
#define G4 256          // 4 * HID
#define BATCH 1024
#define SEQ 512
#define K3_CTAS 391     // ceil(50000/128)
#define HSTRIDE 72      // fp16 h row stride (halfs)

// Scratch (no allocation allowed -> device globals)
__device__ float  g_emb_proj[NUM_CITIES * G4];    // emb @ W_ih^T + bias, 51.2MB
__device__ __half g_hfin_h[BATCH * HID];          // final hidden state (fp16)
__device__ float  g_partial[K3_CTAS * BATCH];     // per-CTA row partial sums
__device__ float  g_rowinv[BATCH];                // 1/rowsum

// ---------------------------------------------------------------------------
// helpers
// ---------------------------------------------------------------------------
__device__ __forceinline__ float fast_ex2(float x) {
    float r; asm("ex2.approx.f32 %0, %1;" : "=f"(r) : "f"(x)); return r;
}
__device__ __forceinline__ float tanh_t(float x) {
    float r; asm("tanh.approx.f32 %0, %1;" : "=f"(r) : "f"(x)); return r;
}
__device__ __forceinline__ u32 h2tanh(u32 v) {            // 2 tanh per MUFU op
    u32 r; asm("tanh.approx.f16x2 %0, %1;" : "=r"(r) : "r"(v)); return r;
}
__device__ __forceinline__ u32 pack_h2(float a, float b) {
    half2 h = __floats2half2_rn(a, b);
    return *reinterpret_cast<u32*>(&h);
}
__device__ __forceinline__ void unpack2(u64 v, float& lo, float& hi) {
    asm("mov.b64 {%0,%1}, %2;" : "=f"(lo), "=f"(hi) : "l"(v));
}
__device__ __forceinline__ u64 pack2(float lo, float hi) {
    u64 v; asm("mov.b64 %0, {%1,%2};" : "=l"(v) : "f"(lo), "f"(hi)); return v;
}
__device__ __forceinline__ void fma2(u64& acc, u64 a, u64 b) {
    asm("fma.rn.f32x2 %0, %1, %2, %0;" : "+l"(acc) : "l"(a), "l"(b));
}
__device__ __forceinline__ void hmma16816(
    float& d0, float& d1, float& d2, float& d3,
    u32 a0, u32 a1, u32 a2, u32 a3, u32 b0, u32 b1)
{
    asm("mma.sync.aligned.m16n8k16.row.col.f32.f16.f16.f32 "
        "{%0,%1,%2,%3}, {%4,%5,%6,%7}, {%8,%9}, {%0,%1,%2,%3};"
        : "+f"(d0), "+f"(d1), "+f"(d2), "+f"(d3)
        : "r"(a0), "r"(a1), "r"(a2), "r"(a3), "r"(b0), "r"(b1));
}
__device__ __forceinline__ u32 w_half2(const float* __restrict__ W, int j, int k) {
    float2 f = *reinterpret_cast<const float2*>(W + j * HID + k);
    half2 h = __float22half2_rn(f);
    return *reinterpret_cast<u32*>(&h);
}

// no-op launch-slot shifter (keeps ncu's fixed sample index on k2)
__global__ void k_nop() {}

// ---------------------------------------------------------------------------
// K1: emb_proj[r][j] = sum_k emb[r][k]*W_ih[j][k] + (b_ih[j]+b_hh[j])
// ---------------------------------------------------------------------------
__global__ void __launch_bounds__(256) k1_embproj(
    const float* __restrict__ emb, const float* __restrict__ W_ih,
    const float* __restrict__ b_ih, const float* __restrict__ b_hh)
{
    __shared__ __align__(16) float es[80][52];
    const int j  = threadIdx.x;
    const int r0 = blockIdx.x * 80;

    u64 wk[26];
    {
        const float2* wr = reinterpret_cast<const float2*>(W_ih + j * 50);
#pragma unroll
        for (int m = 0; m < 25; m++) {
            float2 t = __ldg(&wr[m]);
            wk[m] = pack2(t.x, t.y);
        }
        wk[25] = 0ull;
    }
    const u64 biasp = pack2(b_ih[j] + b_hh[j], 0.0f);

    for (int idx = j; idx < 80 * 50; idx += 256)
        es[idx / 50][idx % 50] = emb[(r0 + idx / 50) * 50 + (idx % 50)];
    if (j < 160) es[j >> 1][50 + (j & 1)] = 0.0f;
    __syncthreads();

#pragma unroll 4
    for (int r = 0; r < 80; r++) {
        u64 acc = biasp;
#pragma unroll
        for (int m = 0; m < 13; m++) {
            ulonglong2 e2 = *reinterpret_cast<const ulonglong2*>(&es[r][m * 4]);
            fma2(acc, e2.x, wk[2 * m]);
            fma2(acc, e2.y, wk[2 * m + 1]);
        }
        float lo, hi; unpack2(acc, lo, hi);
        g_emb_proj[(r0 + r) * G4 + j] = lo + hi;
    }
}

// ---------------------------------------------------------------------------
// K2: LSTM recurrence, gate-aligned HMMA tiling, ONE barrier per step.
// Tokens preloaded as u16 smem; activations via tanh.approx.f16x2 (6 MUFU/step);
// emits fp16 h directly.
// ---------------------------------------------------------------------------
__global__ void __launch_bounds__(128, 2) k2_lstm(
    const int* __restrict__ x, const float* __restrict__ W_hh)
{
    __shared__ __align__(16) __half hS[2][8 * HSTRIDE];
    __shared__ u16 tokS[4][SEQ];

    const int tid  = threadIdx.x;
    const int lane = tid & 31;
    const int w    = tid >> 5;
    const int g    = lane >> 2;
    const int t4   = lane & 3;
    const int b0   = blockIdx.x * 4;

    const int kc = 16 * w + g + ((t4 >> 1) ? 8 : 0);
    const int bA = (t4 & 1) * 2;
    const int bB = bA + 1;

    u32 A[4][4][4];
#pragma unroll
    for (int G = 0; G < 4; G++) {
        const int j = 64 * G + 16 * w + g;
#pragma unroll
        for (int K = 0; K < 4; K++) {
            const int c = 16 * K + 2 * t4;
            A[G][K][0] = w_half2(W_hh, j,     c);
            A[G][K][1] = w_half2(W_hh, j + 8, c);
            A[G][K][2] = w_half2(W_hh, j,     c + 8);
            A[G][K][3] = w_half2(W_hh, j + 8, c + 8);
        }
    }

    {
        __half* hz = &hS[0][0];
        for (int i = tid; i < 2 * 8 * HSTRIDE; i += 128) hz[i] = __float2half(0.0f);
    }
    // preload all tokens (u16; NUM_CITIES < 65536)
    for (int i = tid; i < 4 * SEQ; i += 128) {
        const int b = i >> 9, t = i & (SEQ - 1);
        tokS[b][t] = (u16)__ldg(&x[(b0 + b) * SEQ + t]);
    }
    // gx(0) straight from x
    float gxA[4], gxB[4];
    {
        const int tokA = __ldg(&x[(b0 + bA) * SEQ]);
        const int tokB = __ldg(&x[(b0 + bB) * SEQ]);
#pragma unroll
        for (int G = 0; G < 4; G++) {
            gxA[G] = __ldg(g_emb_proj + (size_t)tokA * G4 + 64 * G + kc);
            gxB[G] = __ldg(g_emb_proj + (size_t)tokB * G4 + 64 * G + kc);
        }
    }

    float cA = 0.0f, cB = 0.0f, hA = 0.0f, hB = 0.0f;

    __syncthreads();

    for (int t = 0; t < SEQ; t++) {
        const int buf = t & 1;
        const __half* hb = hS[buf];

        // ---- 16 HMMA: all 4 gates for this warp's k-slice ----
        float D[4][4];
#pragma unroll
        for (int G = 0; G < 4; G++) {
            D[G][0] = 0.f; D[G][1] = 0.f; D[G][2] = 0.f; D[G][3] = 0.f;
        }
#pragma unroll
        for (int K = 0; K < 4; K++) {
            const int kk = 16 * K + 2 * t4;
            u32 bb0 = *reinterpret_cast<const u32*>(&hb[g * HSTRIDE + kk]);
            u32 bb1 = *reinterpret_cast<const u32*>(&hb[g * HSTRIDE + kk + 8]);
#pragma unroll
            for (int G = 0; G < 4; G++)
                hmma16816(D[G][0], D[G][1], D[G][2], D[G][3],
                          A[G][K][0], A[G][K][1], A[G][K][2], A[G][K][3], bb0, bb1);
        }

        // ---- prefetch gx(t+1) (tokens from smem; last-step value unused) ----
        float nA[4], nB[4];
        {
            const int tn = (t + 1 < SEQ) ? (t + 1) : (SEQ - 1);
            const int tokA = tokS[bA][tn];
            const int tokB = tokS[bB][tn];
#pragma unroll
            for (int G = 0; G < 4; G++) {
                nA[G] = __ldg(g_emb_proj + (size_t)tokA * G4 + 64 * G + kc);
                nB[G] = __ldg(g_emb_proj + (size_t)tokB * G4 + 64 * G + kc);
            }
        }

        // ---- shfl rebalance: lanes t4>=2 take the (g+8) rows ----
        float xA[4], xB[4];
#pragma unroll
        for (int G = 0; G < 4; G++) {
            float sA = __shfl_xor_sync(0xffffffffu, D[G][2], 2);
            float sB = __shfl_xor_sync(0xffffffffu, D[G][3], 2);
            xA[G] = ((t4 < 2) ? D[G][0] : sA) + gxA[G];
            xB[G] = ((t4 < 2) ? D[G][1] : sB) + gxB[G];
        }

        // ---- packed activations: 4 x tanh.f16x2 covers all 8 gate values ----
        {
            u32 ti = h2tanh(pack_h2(0.5f * xA[0], 0.5f * xB[0]));
            u32 tf = h2tanh(pack_h2(0.5f * xA[1], 0.5f * xB[1]));
            u32 tg = h2tanh(pack_h2(xA[2], xB[2]));
            u32 to = h2tanh(pack_h2(0.5f * xA[3], 0.5f * xB[3]));
            half2 hti = *reinterpret_cast<half2*>(&ti);
            half2 htf = *reinterpret_cast<half2*>(&tf);
            half2 htg = *reinterpret_cast<half2*>(&tg);
            half2 hto = *reinterpret_cast<half2*>(&to);

            float iA = fmaf(0.5f, __low2float(hti), 0.5f);
            float iB = fmaf(0.5f, __high2float(hti), 0.5f);
            float fA = fmaf(0.5f, __low2float(htf), 0.5f);
            float fB = fmaf(0.5f, __high2float(htf), 0.5f);
            float gA = __low2float(htg);
            float gB = __high2float(htg);
            float oA = fmaf(0.5f, __low2float(hto), 0.5f);
            float oB = fmaf(0.5f, __high2float(hto), 0.5f);

            cA = fmaf(fA, cA, iA * gA);
            cB = fmaf(fB, cB, iB * gB);
            hA = oA * tanh_t(cA);
            hB = oB * tanh_t(cB);
        }

        // ---- publish h(t+1), roll gx regs ----
        {
            __half* hn = hS[buf ^ 1];
            hn[bA * HSTRIDE + kc] = __float2half(hA);
            hn[bB * HSTRIDE + kc] = __float2half(hB);
        }
#pragma unroll
        for (int G = 0; G < 4; G++) { gxA[G] = nA[G]; gxB[G] = nB[G]; }

        __syncthreads();
    }

    g_hfin_h[(b0 + bA) * HID + kc] = __float2half(hA);
    g_hfin_h[(b0 + bB) * HID + kc] = __float2half(hB);
}

// ---------------------------------------------------------------------------
// K3: tensor-core FC, two-pass. store=0: exp row-sums only -> g_partial.
// store=1: recompute, scale by g_rowinv, write normalized output once.
// ---------------------------------------------------------------------------
__global__ void __launch_bounds__(256) k3_fc(
    const float* __restrict__ W_fc, const float* __restrict__ b_fc,
    float* __restrict__ out, int store)
{
    __shared__ __align__(16) __half hs[64 * HSTRIDE];
    __shared__ float ws[8][64];
    __shared__ float riS[64];

    const int tid  = threadIdx.x;
    const int lane = tid & 31;
    const int w    = tid >> 5;
    const int g    = lane >> 2;
    const int t4   = lane & 3;

    const int cb   = blockIdx.x * 128;
    const int j1   = cb + 16 * w + g;
    const int j2   = j1 + 8;
    const bool v1  = (j1 < NUM_CITIES);
    const bool v2  = (j2 < NUM_CITIES);

    u32 A[4][4];
#pragma unroll
    for (int K = 0; K < 4; K++) {
        const int c = 16 * K + 2 * t4;
        A[K][0] = v1 ? w_half2(W_fc, j1, c)     : 0u;
        A[K][1] = v2 ? w_half2(W_fc, j2, c)     : 0u;
        A[K][2] = v1 ? w_half2(W_fc, j1, c + 8) : 0u;
        A[K][3] = v2 ? w_half2(W_fc, j2, c + 8) : 0u;
    }
    const float bias1 = v1 ? __ldg(&b_fc[j1]) : 0.0f;
    const float bias2 = v2 ? __ldg(&b_fc[j2]) : 0.0f;

    const u32* hsrc = reinterpret_cast<const u32*>(g_hfin_h);

    for (int chunk = 0; chunk < 16; chunk++) {
        const int cb64 = chunk * 64;
        __syncthreads();
        // stage h chunk (already fp16): 64 rows x 32 u32
        for (int i = tid; i < 64 * 32; i += 256) {
            const int r = i >> 5;
            const int cp = i & 31;
            *reinterpret_cast<u32*>(&hs[r * HSTRIDE + 2 * cp]) =
                __ldg(&hsrc[(cb64 + r) * 32 + cp]);
        }
        if (store && tid < 64) riS[tid] = g_rowinv[cb64 + tid];
        __syncthreads();

#pragma unroll
        for (int nt = 0; nt < 8; nt++) {
            const int nb = cb64 + nt * 8;
            float d0 = 0.f, d1 = 0.f, d2 = 0.f, d3 = 0.f;
#pragma unroll
            for (int K = 0; K < 4; K++) {
                const int kk = 16 * K + 2 * t4;
                const __half* hrow = &hs[(nt * 8 + g) * HSTRIDE];
                u32 bb0 = *reinterpret_cast<const u32*>(&hrow[kk]);
                u32 bb1 = *reinterpret_cast<const u32*>(&hrow[kk + 8]);
                hmma16816(d0, d1, d2, d3, A[K][0], A[K][1], A[K][2], A[K][3], bb0, bb1);
            }
            const float LOG2E = 1.4426950408889634f;
            float e0 = v1 ? fast_ex2((d0 + bias1) * LOG2E) : 0.0f;
            float e1 = v1 ? fast_ex2((d1 + bias1) * LOG2E) : 0.0f;
            float e2 = v2 ? fast_ex2((d2 + bias2) * LOG2E) : 0.0f;
            float e3 = v2 ? fast_ex2((d3 + bias2) * LOG2E) : 0.0f;

            if (store) {
                const float r0v = riS[nt * 8 + 2 * t4];
                const float r1v = riS[nt * 8 + 2 * t4 + 1];
                const size_t rA = (size_t)(nb + 2 * t4) * NUM_CITIES;
                const size_t rB = (size_t)(nb + 2 * t4 + 1) * NUM_CITIES;
                if (v1) { __stcs(&out[rA + j1], e0 * r0v); __stcs(&out[rB + j1], e1 * r1v); }
                if (v2) { __stcs(&out[rA + j2], e2 * r0v); __stcs(&out[rB + j2], e3 * r1v); }
            } else {
                float s0 = e0 + e2;
                float s1 = e1 + e3;
#pragma unroll
                for (int m = 4; m <= 16; m <<= 1) {
                    s0 += __shfl_xor_sync(0xffffffffu, s0, m);
                    s1 += __shfl_xor_sync(0xffffffffu, s1, m);
                }
                if (g == 0) {
                    ws[w][nt * 8 + 2 * t4]     = s0;
                    ws[w][nt * 8 + 2 * t4 + 1] = s1;
                }
            }
        }
        if (!store) {
            __syncthreads();
            if (tid < 64) {
                float s = 0.0f;
#pragma unroll
                for (int ww = 0; ww < 8; ww++) s += ws[ww][tid];
                g_partial[blockIdx.x * BATCH + cb64 + tid] = s;
            }
        }
    }
}

// ---------------------------------------------------------------------------
// K3c: exact row-sum inverses. One warp per batch row.
// ---------------------------------------------------------------------------
__global__ void __launch_bounds__(128) k3c_inv()
{
    const int warp = (blockIdx.x * 128 + threadIdx.x) >> 5;   // 0..1023
    const int lane = threadIdx.x & 31;
    float s = 0.0f;
    for (int cta = lane; cta < K3_CTAS; cta += 32)
        s += g_partial[cta * BATCH + warp];
    s += __shfl_xor_sync(0xffffffffu, s, 16);
    s += __shfl_xor_sync(0xffffffffu, s, 8);
    s += __shfl_xor_sync(0xffffffffu, s, 4);
    s += __shfl_xor_sync(0xffffffffu, s, 2);
    s += __shfl_xor_sync(0xffffffffu, s, 1);
    if (lane == 0) g_rowinv[warp] = 1.0f / s;
}

// ---------------------------------------------------------------------------
extern "C" void kernel_launch(void* const* d_in, const int* in_sizes, int n_in,
                              void* d_out, int out_size)
{
    (void)in_sizes; (void)n_in; (void)out_size;
    const int*   x    = (const int*)  d_in[0];
    const float* emb  = (const float*)d_in[1];
    const float* W_ih = (const float*)d_in[2];
    const float* W_hh = (const float*)d_in[3];
    const float* b_ih = (const float*)d_in[4];
    const float* b_hh = (const float*)d_in[5];
    const float* W_fc = (const float*)d_in[6];
    const float* b_fc = (const float*)d_in[7];
    float* out = (float*)d_out;

    k1_embproj<<<NUM_CITIES / 80, 256>>>(emb, W_ih, b_ih, b_hh);
    k_nop<<<1, 32>>>();
    k_nop<<<1, 32>>>();
    k2_lstm<<<BATCH / 4, 128>>>(x, W_hh);          // launch idx 3 -> profiled
    k3_fc<<<K3_CTAS, 256>>>(W_fc, b_fc, out, 0);   // pass 1: sums
    k3c_inv<<<256, 128>>>();
    k3_fc<<<K3_CTAS, 256>>>(W_fc, b_fc, out, 1);   // pass 2: normalized store
}